// round 16
// baseline (speedup 1.0000x reference)
#include <cuda_runtime.h>
#include <cuda_fp16.h>
#include <math.h>
#include <stdint.h>

// ---------------- problem constants ----------------
#define BB    16
#define NP1   65
#define NT    (BB*NP1)      // 1040 tokens
#define MM    256
#define DD    512
#define NH    8
#define DH    64
#define LL    3
#define DFFN  2048
#define U_SIZE (NT*MM)

// weight-split buffer offsets (elements)
#define OFF_QKV 0
#define SZ_QKV  (LL*3*DD*DD)
#define OFF_OUT (OFF_QKV + SZ_QKV)
#define SZ_OUT  (LL*DD*DD)
#define OFF_FF1 (OFF_OUT + SZ_OUT)
#define SZ_FF1  (LL*DFFN*DD)
#define OFF_FF2 (OFF_FF1 + SZ_FF1)
#define SZ_FF2  (LL*DD*DFFN)
#define OFF_U   (OFF_FF2 + SZ_FF2)
#define SZ_U    (MM*DD)
#define OFF_H   (OFF_U + SZ_U)
#define SZ_H    (MM*DD)
#define WTOT    (OFF_H + SZ_H)

// ---------------- scratch ----------------
__device__ float  g_xs  [NT*DD];
__device__ __half g_xsh [NT*DD];
__device__ float  g_buf [NT*3*DD];
__device__ __half g_ath [NT*DD];
__device__ __half g_ffh [NT*DFFN];
__device__ float  g_hraw[NT*MM];
__device__ __half g_whi[WTOT];
__device__ __half g_wlo[WTOT];

// ---------------- helpers ----------------
__device__ __forceinline__ float gelu_exact(float x) {
    return 0.5f * x * (1.0f + erff(x * 0.70710678118654752440f));
}
__device__ __forceinline__ float blockSum256(float v, float* sm) {
    int tid = threadIdx.x;
    #pragma unroll
    for (int o = 16; o > 0; o >>= 1) v += __shfl_down_sync(0xffffffffu, v, o);
    if ((tid & 31) == 0) sm[tid >> 5] = v;
    __syncthreads();
    if (tid < 8) {
        v = sm[tid];
        #pragma unroll
        for (int o = 4; o > 0; o >>= 1) v += __shfl_down_sync(0xffu, v, o);
        if (tid == 0) sm[0] = v;
    }
    __syncthreads();
    float r = sm[0];
    __syncthreads();
    return r;
}
__device__ __forceinline__ float warpSum(float v) {
    #pragma unroll
    for (int o = 16; o > 0; o >>= 1) v += __shfl_xor_sync(0xffffffffu, v, o);
    return v;
}
__device__ __forceinline__ void mma16h(float* d, const uint32_t* a, const uint32_t* b) {
    asm volatile(
        "mma.sync.aligned.m16n8k16.row.col.f32.f16.f16.f32 "
        "{%0,%1,%2,%3}, {%4,%5,%6,%7}, {%8,%9}, {%0,%1,%2,%3};"
        : "+f"(d[0]), "+f"(d[1]), "+f"(d[2]), "+f"(d[3])
        : "r"(a[0]), "r"(a[1]), "r"(a[2]), "r"(a[3]), "r"(b[0]), "r"(b[1]));
}
__device__ __forceinline__ void ldsm4(uint32_t* r, uint32_t addr) {
    asm volatile("ldmatrix.sync.aligned.m8n8.x4.shared.b16 {%0,%1,%2,%3}, [%4];"
                 : "=r"(r[0]), "=r"(r[1]), "=r"(r[2]), "=r"(r[3]) : "r"(addr));
}
__device__ __forceinline__ uint32_t smem_u32(const void* p) {
    uint32_t a;
    asm("{ .reg .u64 t; cvta.to.shared.u64 t, %1; cvt.u32.u64 %0, t; }" : "=r"(a) : "l"(p));
    return a;
}
__device__ __forceinline__ void cp16(uint32_t dst, const void* src, unsigned ok) {
    asm volatile("cp.async.cg.shared.global [%0], [%1], 16, %2;"
                 :: "r"(dst), "l"(src), "r"(ok));
}
__device__ __forceinline__ void cp16u(uint32_t dst, const void* src) {
    asm volatile("cp.async.cg.shared.global [%0], [%1], 16;"
                 :: "r"(dst), "l"(src));
}

// ---------------- fused weight split (fp16 hi/lo) ----------------
#define B0 (SZ_QKV/4)
#define B1 (B0 + SZ_OUT/4)
#define B2 (B1 + SZ_FF1/4)
#define B3 (B2 + SZ_FF2/4)
#define B4 (B3 + SZ_U/4)
#define B5 (B4 + SZ_H/4)
__global__ void split_all(const float4* __restrict__ w_qkv, const float4* __restrict__ w_out,
                          const float4* __restrict__ w_ff1, const float4* __restrict__ w_ff2,
                          const float4* __restrict__ w_u,   const float4* __restrict__ w_h) {
    __half2* hi = (__half2*)g_whi;
    __half2* lo = (__half2*)g_wlo;
    for (int i = blockIdx.x*blockDim.x + threadIdx.x; i < B5; i += gridDim.x*blockDim.x) {
        const float4* src; int j;
        if      (i < B0) { src = w_qkv; j = i; }
        else if (i < B1) { src = w_out; j = i - B0; }
        else if (i < B2) { src = w_ff1; j = i - B1; }
        else if (i < B3) { src = w_ff2; j = i - B2; }
        else if (i < B4) { src = w_u;   j = i - B3; }
        else             { src = w_h;   j = i - B4; }
        float4 v = src[j];
        __half hx = __float2half_rn(v.x), hy = __float2half_rn(v.y);
        __half hz = __float2half_rn(v.z), hw = __float2half_rn(v.w);
        __half lx = __float2half_rn(v.x - __half2float(hx));
        __half ly = __float2half_rn(v.y - __half2float(hy));
        __half lz = __float2half_rn(v.z - __half2float(hz));
        __half lw = __float2half_rn(v.w - __half2float(hw));
        hi[2*i]   = __halves2half2(hx, hy);
        hi[2*i+1] = __halves2half2(hz, hw);
        lo[2*i]   = __halves2half2(lx, ly);
        lo[2*i+1] = __halves2half2(lz, lw);
    }
}

// ---------------- embed ----------------
__global__ void embed_kernel(const float* __restrict__ marg,
                             const float* __restrict__ conv_w,
                             const float* __restrict__ conv_b,
                             const float* __restrict__ fc_w,
                             const float* __restrict__ fc_b,
                             const float* __restrict__ ln_g,
                             const float* __restrict__ ln_b,
                             const float* __restrict__ pos) {
    int t   = blockIdx.x;
    int tid = threadIdx.x;
    __shared__ float red[8];
    __shared__ float e128[128];

    const float* x = marg + (size_t)t * MM;
    float S = blockSum256(x[tid], red);

    if (tid < 128) {
        float x0 = x[0], x1 = x[1], x254 = x[254], x255 = x[255];
        float T0 = S - x254 - x255;
        float T1 = S - x255;
        float T2 = S;
        float T3 = S - x0;
        float T4 = S - x0 - x1;
        const float* w = conv_w + tid * 5;
        e128[tid] = conv_b[tid] +
            (w[0]*T0 + w[1]*T1 + w[2]*T2 + w[3]*T3 + w[4]*T4) * (1.0f/256.0f);
    }
    __syncthreads();

    float y0 = fc_b[tid];
    float y1 = fc_b[tid + 256];
    #pragma unroll 8
    for (int k = 0; k < 128; k++) {
        float e = e128[k];
        y0 = fmaf(e, fc_w[k*DD + tid],       y0);
        y1 = fmaf(e, fc_w[k*DD + tid + 256], y1);
    }
    float s  = blockSum256(y0 + y1, red);
    float mu = s * (1.0f/512.0f);
    float d0 = y0 - mu, d1 = y1 - mu;
    float vs = blockSum256(d0*d0 + d1*d1, red);
    float inv = rsqrtf(vs * (1.0f/512.0f) + 1e-5f);

    int p = t % NP1;
    float z0 = gelu_exact(d0*inv*ln_g[tid]       + ln_b[tid])       + pos[p*DD + tid];
    float z1 = gelu_exact(d1*inv*ln_g[tid + 256] + ln_b[tid + 256]) + pos[p*DD + tid + 256];
    size_t i0 = (size_t)t*DD + tid, i1 = i0 + 256;
    g_xs[i0] = z0; g_xs[i1] = z1;
    g_xsh[i0] = __float2half_rn(z0);
    g_xsh[i1] = __float2half_rn(z1);
}

// ---------------- 2-term fp16 mma.sync GEMM, BM=128, BK=32, 4-stage ring ----------------
#define SSTH 40
template <int BN, int MODE>
__global__ void __launch_bounds__(256, 2)
gemm_f16(const __half* __restrict__ A,
         const __half* __restrict__ Whi, const __half* __restrict__ Wlo,
         const float* __restrict__ bias, const float* __restrict__ bias2,
         float* __restrict__ C, __half* __restrict__ Ch, float* __restrict__ C2,
         int M, int N, int K) {
    constexpr int MFRAG = 2;
    constexpr int NFRAG = BN / 16;
    constexpr int A_E   = 128 * SSTH;
    constexpr int B_E   = BN * SSTH;
    constexpr int STAGE_E = A_E + 2*B_E;

    extern __shared__ __align__(16) __half sm[];
    const int tid  = threadIdx.x;
    const int warp = tid >> 5, lane = tid & 31;
    const int gid  = lane >> 2, tig = lane & 3;
    const int m_warp = (warp & 3) * 32;
    const int n_warp = (warp >> 2) * (BN/2);
    const int bn = blockIdx.x * BN;
    const int bm = blockIdx.y * 128;

    float acc[MFRAG][NFRAG][4];
    #pragma unroll
    for (int mi = 0; mi < MFRAG; mi++)
        #pragma unroll
        for (int ni = 0; ni < NFRAG; ni++)
            #pragma unroll
            for (int r = 0; r < 4; r++) acc[mi][ni][r] = 0.0f;

    const uint32_t smb = smem_u32(sm);

    const int laneA_row = m_warp + ((lane >> 3) & 1) * 8 + (lane & 7);
    const int laneA_col = (lane >> 4) * 8;
    const int laneB_row = n_warp + ((lane >> 4) & 1) * 8 + (lane & 7);
    const int laneB_col = ((lane >> 3) & 1) * 8;

    const int rowA = tid >> 2;
    const int chkA = tid & 3;
    const int T = K >> 5;

    auto load_tile = [&](int stage, int k0) {
        uint32_t sb = smb + (uint32_t)stage * (STAGE_E*2);
        #pragma unroll
        for (int i = 0; i < 2; i++) {
            int row = rowA + i*64;
            int gr  = bm + row;
            unsigned ok = (gr < M) ? 16u : 0u;
            size_t go = (size_t)(gr < M ? gr : 0) * K + k0 + chkA*8;
            cp16(sb + (uint32_t)(row*SSTH + chkA*8)*2, A + go, ok);
        }
        {
            int nb = BN * 4;
            if (BN == 64 || tid < nb) {
                int row = (BN == 64) ? rowA : (tid >> 2);
                int chk = (BN == 64) ? chkA : (tid & 3);
                size_t go = (size_t)(bn + row) * K + k0 + chk*8;
                uint32_t d = sb + (uint32_t)(A_E + row*SSTH + chk*8)*2;
                cp16u(d,         Whi + go);
                cp16u(d + B_E*2, Wlo + go);
            }
        }
        asm volatile("cp.async.commit_group;");
    };

    load_tile(0, 0);
    if (T > 1) load_tile(1, 32);
    if (T > 2) load_tile(2, 64);

    for (int t = 0; t < T; t++) {
        int rem = T - 1 - t; if (rem > 2) rem = 2;
        if      (rem == 2) asm volatile("cp.async.wait_group 2;");
        else if (rem == 1) asm volatile("cp.async.wait_group 1;");
        else               asm volatile("cp.async.wait_group 0;");
        __syncthreads();
        if (t + 3 < T) load_tile((t + 3) & 3, (t + 3) * 32);

        const uint32_t stage_b = smb + (uint32_t)(t & 3) * (STAGE_E*2);

        #pragma unroll
        for (int kf = 0; kf < 2; kf++) {
            const int kcol = kf * 16;
            uint32_t ah[MFRAG][4];
            uint32_t aoff = stage_b + (uint32_t)(laneA_row*SSTH + kcol + laneA_col)*2;
            #pragma unroll
            for (int mi = 0; mi < MFRAG; mi++)
                ldsm4(ah[mi], aoff + (uint32_t)(mi*16*SSTH)*2);

            uint32_t bh[NFRAG][2], bl[NFRAG][2];
            uint32_t boff = stage_b + (uint32_t)(A_E)*2
                          + (uint32_t)(laneB_row*SSTH + kcol + laneB_col)*2;
            #pragma unroll
            for (int ng = 0; ng < NFRAG/2; ng++) {
                uint32_t rb[4], rl[4];
                ldsm4(rb, boff + (uint32_t)(ng*16*SSTH)*2);
                ldsm4(rl, boff + (uint32_t)(ng*16*SSTH)*2 + B_E*2);
                bh[2*ng][0]   = rb[0]; bh[2*ng][1]   = rb[1];
                bh[2*ng+1][0] = rb[2]; bh[2*ng+1][1] = rb[3];
                bl[2*ng][0]   = rl[0]; bl[2*ng][1]   = rl[1];
                bl[2*ng+1][0] = rl[2]; bl[2*ng+1][1] = rl[3];
            }
            #pragma unroll
            for (int mi = 0; mi < MFRAG; mi++)
                #pragma unroll
                for (int ni = 0; ni < NFRAG; ni++) mma16h(acc[mi][ni], ah[mi], bh[ni]);
            #pragma unroll
            for (int mi = 0; mi < MFRAG; mi++)
                #pragma unroll
                for (int ni = 0; ni < NFRAG; ni++) mma16h(acc[mi][ni], ah[mi], bl[ni]);
        }
    }

    #pragma unroll
    for (int mi = 0; mi < MFRAG; mi++) {
        #pragma unroll
        for (int ni = 0; ni < NFRAG; ni++) {
            int col = bn + n_warp + ni*8 + tig*2;
            float* a4 = acc[mi][ni];
            #pragma unroll
            for (int half_ = 0; half_ < 2; half_++) {
                int r = bm + m_warp + mi*16 + gid + half_*8;
                if (r >= M) continue;
                float v0 = a4[half_*2];
                float v1 = a4[half_*2+1];
                if (MODE == 0) {
                    v0 += __ldg(bias + col); v1 += __ldg(bias + col + 1);
                    *(float2*)&C[(size_t)r*N + col] = make_float2(v0, v1);
                } else if (MODE == 1) {
                    v0 = gelu_exact(v0 + __ldg(bias + col));
                    v1 = gelu_exact(v1 + __ldg(bias + col + 1));
                    *(__half2*)&Ch[(size_t)r*N + col] =
                        __halves2half2(__float2half_rn(v0), __float2half_rn(v1));
                } else {
                    if (col < 256) {
                        v0 += __ldg(bias + col); v1 += __ldg(bias + col + 1);
                        *(float2*)&C[(size_t)r*MM + col] = make_float2(v0, v1);
                    } else {
                        v0 += __ldg(bias2 + col - 256); v1 += __ldg(bias2 + col - 255);
                        *(float2*)&C2[(size_t)r*MM + col - 256] = make_float2(v0, v1);
                    }
                }
            }
        }
    }
}

// ---------------- attention: one 512-thread block per (b,h), cp.async staging ----------------
#define QPAD 68
#define ATT_SM (4 * NP1 * QPAD * 4)   // sq, sk, sv, ss = 70720 bytes
__global__ void __launch_bounds__(512, 1) attn_kernel(const float* __restrict__ qkv) {
    int b = blockIdx.x, h = blockIdx.y;
    extern __shared__ float asm_[];
    float* sq = asm_;
    float* sk = sq + NP1*QPAD;
    float* sv = sk + NP1*QPAD;
    float* ss = sv + NP1*QPAD;
    int tid = threadIdx.x;
    int warp = tid >> 5, lane = tid & 31;

    // stage Q, K, V via cp.async (16B chunks, no register round-trip)
    const float* base_b = qkv + (size_t)b * NP1 * (3*DD) + h*DH;
    const uint32_t sqb = smem_u32(sq);
    const uint32_t skb = smem_u32(sk);
    const uint32_t svb = smem_u32(sv);
    for (int idx = tid; idx < NP1*16; idx += 512) {
        int t = idx >> 4, d4 = idx & 15;
        const float4* p = (const float4*)(base_b + (size_t)t*(3*DD));
        uint32_t off = (uint32_t)(t*QPAD + d4*4) * 4;
        cp16u(sqb + off, p + d4);
        cp16u(skb + off, p + 128 + d4);
        cp16u(svb + off, p + 256 + d4);
    }
    asm volatile("cp.async.commit_group;");
    asm volatile("cp.async.wait_group 0;");
    __syncthreads();

    // scores
    const float scale = 0.125f;
    for (int idx = tid; idx < NP1*NP1; idx += 512) {
        int r = idx / NP1, c = idx - r*NP1;
        const float4* qr = (const float4*)&sq[r*QPAD];
        const float4* kr = (const float4*)&sk[c*QPAD];
        float s0 = 0.f, s1 = 0.f, s2 = 0.f, s3 = 0.f;
        #pragma unroll
        for (int d = 0; d < 16; d += 4) {
            float4 a0 = qr[d],   b0 = kr[d];
            float4 a1 = qr[d+1], b1 = kr[d+1];
            float4 a2 = qr[d+2], b2 = kr[d+2];
            float4 a3 = qr[d+3], b3 = kr[d+3];
            s0 += a0.x*b0.x + a0.y*b0.y + a0.z*b0.z + a0.w*b0.w;
            s1 += a1.x*b1.x + a1.y*b1.y + a1.z*b1.z + a1.w*b1.w;
            s2 += a2.x*b2.x + a2.y*b2.y + a2.z*b2.z + a2.w*b2.w;
            s3 += a3.x*b3.x + a3.y*b3.y + a3.z*b3.z + a3.w*b3.w;
        }
        ss[r*QPAD + c] = (s0 + s1 + s2 + s3) * scale;
    }
    __syncthreads();

    // warp-parallel softmax: 65 rows over 16 warps
    for (int r = warp; r < NP1; r += 16) {
        float* rowp = ss + r*QPAD;
        float m = -1e30f;
        for (int c = lane; c < NP1; c += 32) m = fmaxf(m, rowp[c]);
        #pragma unroll
        for (int o = 16; o > 0; o >>= 1) m = fmaxf(m, __shfl_xor_sync(0xffffffffu, m, o));
        float s = 0.0f;
        for (int c = lane; c < NP1; c += 32) { float e = __expf(rowp[c] - m); rowp[c] = e; s += e; }
        #pragma unroll
        for (int o = 16; o > 0; o >>= 1) s += __shfl_xor_sync(0xffffffffu, s, o);
        float inv = 1.0f / s;
        for (int c = lane; c < NP1; c += 32) rowp[c] *= inv;
    }
    __syncthreads();

    // O = att @ V, float4 over d; sv reads broadcast across warp
    for (int idx = tid; idx < NP1*16; idx += 512) {
        int r = idx >> 4, d4 = (idx & 15) * 4;
        const float* rowp = ss + r*QPAD;
        float4 o0 = make_float4(0.f, 0.f, 0.f, 0.f);
        float4 o1 = make_float4(0.f, 0.f, 0.f, 0.f);
        int t = 0;
        #pragma unroll 8
        for (; t + 2 <= NP1; t += 2) {
            float w0 = rowp[t], w1 = rowp[t+1];
            float4 v0 = *(const float4*)&sv[t*QPAD + d4];
            float4 v1 = *(const float4*)&sv[(t+1)*QPAD + d4];
            o0.x = fmaf(w0, v0.x, o0.x); o0.y = fmaf(w0, v0.y, o0.y);
            o0.z = fmaf(w0, v0.z, o0.z); o0.w = fmaf(w0, v0.w, o0.w);
            o1.x = fmaf(w1, v1.x, o1.x); o1.y = fmaf(w1, v1.y, o1.y);
            o1.z = fmaf(w1, v1.z, o1.z); o1.w = fmaf(w1, v1.w, o1.w);
        }
        {
            float w0 = rowp[64];
            float4 v0 = *(const float4*)&sv[64*QPAD + d4];
            o0.x = fmaf(w0, v0.x, o0.x); o0.y = fmaf(w0, v0.y, o0.y);
            o0.z = fmaf(w0, v0.z, o0.z); o0.w = fmaf(w0, v0.w, o0.w);
        }
        __half2 p0 = __halves2half2(__float2half_rn(o0.x + o1.x), __float2half_rn(o0.y + o1.y));
        __half2 p1 = __halves2half2(__float2half_rn(o0.z + o1.z), __float2half_rn(o0.w + o1.w));
        size_t gi = (size_t)(b*NP1 + r)*DD + h*DH + d4;
        *(__half2*)&g_ath[gi]     = p0;
        *(__half2*)&g_ath[gi + 2] = p1;
    }
}

// ---------------- residual add + layernorm: warp-per-row, grid 130 ----------------
__global__ void __launch_bounds__(256) resid_ln_kernel(float* __restrict__ xs,
                                const float* __restrict__ add,
                                const float* __restrict__ g,
                                const float* __restrict__ bb) {
    int warp = threadIdx.x >> 5, lane = threadIdx.x & 31;
    int t = blockIdx.x * 8 + warp;          // NT = 130*8 exactly
    size_t base = (size_t)t * DD;

    float4 v[4];
    #pragma unroll
    for (int k = 0; k < 4; k++) {
        int c = (lane + k*32) * 4;
        float4 a  = *(const float4*)&xs[base + c];
        float4 ad = *(const float4*)&add[base + c];
        v[k] = make_float4(a.x+ad.x, a.y+ad.y, a.z+ad.z, a.w+ad.w);
    }
    float s = 0.f;
    #pragma unroll
    for (int k = 0; k < 4; k++) s += (v[k].x + v[k].y) + (v[k].z + v[k].w);
    s = warpSum(s);
    float mu = s * (1.0f/512.0f);
    float vs = 0.f;
    #pragma unroll
    for (int k = 0; k < 4; k++) {
        float dx = v[k].x-mu, dy = v[k].y-mu, dz = v[k].z-mu, dw = v[k].w-mu;
        vs += dx*dx + dy*dy + dz*dz + dw*dw;
    }
    vs = warpSum(vs);
    float inv = rsqrtf(vs * (1.0f/512.0f) + 1e-5f);

    #pragma unroll
    for (int k = 0; k < 4; k++) {
        int c = (lane + k*32) * 4;
        float4 gg = *(const float4*)&g[c];
        float4 bv = *(const float4*)&bb[c];
        float z0 = (v[k].x - mu)*inv*gg.x + bv.x;
        float z1 = (v[k].y - mu)*inv*gg.y + bv.y;
        float z2 = (v[k].z - mu)*inv*gg.z + bv.z;
        float z3 = (v[k].w - mu)*inv*gg.w + bv.w;
        *(float4*)&xs[base + c] = make_float4(z0, z1, z2, z3);
        __half2 h0 = __halves2half2(__float2half_rn(z0), __float2half_rn(z1));
        __half2 h1 = __halves2half2(__float2half_rn(z2), __float2half_rn(z3));
        *(__half2*)&g_xsh[base + c]     = h0;
        *(__half2*)&g_xsh[base + c + 2] = h1;
    }
}

// ---------------- final drift / correction -> h_pot ----------------
__global__ void hpot_kernel(const float* __restrict__ marg,
                            const float* __restrict__ xg,
                            float* __restrict__ out) {
    int b = blockIdx.x, n = blockIdx.y;
    int i = threadIdx.x;
    __shared__ float red[8];

    float x0   = __ldg(xg);
    float xend = __ldg(xg + 255);
    float delta = (xend - x0) * (1.0f/255.0f);
    float xi = __ldg(xg + i);

    float hr = g_hraw[(size_t)(b*NP1 + n)*MM + i];
    float u  = hr * 100.0f * delta;
    float Mv;
    if (fabsf(u) < 1e-3f) {
        Mv = 127.5f - u*5461.25f + u*u*u*5965232.4f;
    } else {
        Mv = 1.0f/expm1f(u) - 256.0f/expm1f(256.0f*u);
    }
    float drift = (x0 + delta*Mv) - xi;

    float mu = marg[(size_t)(b*NP1 + n)*MM + i];
    float wd = blockSum256(mu * drift, red);
    float wm = blockSum256(mu, red);
    float corr = wd / (wm + 1e-8f);
    out[U_SIZE + (size_t)(b*64 + n)*MM + i] = hr - corr;
}

// ---------------- launch ----------------
extern "C" void kernel_launch(void* const* d_in, const int* in_sizes, int n_in,
                              void* d_out, int out_size) {
    const float* marg   = (const float*)d_in[0];
    const float* xg     = (const float*)d_in[1];
    const float* conv_w = (const float*)d_in[2];
    const float* conv_b = (const float*)d_in[3];
    const float* fc_w   = (const float*)d_in[4];
    const float* fc_b   = (const float*)d_in[5];
    const float* ln0_g  = (const float*)d_in[6];
    const float* ln0_b  = (const float*)d_in[7];
    const float* pos    = (const float*)d_in[8];
    const float* qkv_w  = (const float*)d_in[9];
    const float* qkv_b  = (const float*)d_in[10];
    const float* out_w  = (const float*)d_in[11];
    const float* out_b  = (const float*)d_in[12];
    const float* ln1_g  = (const float*)d_in[13];
    const float* ln1_b  = (const float*)d_in[14];
    const float* ff1_w  = (const float*)d_in[15];
    const float* ff1_b  = (const float*)d_in[16];
    const float* ff2_w  = (const float*)d_in[17];
    const float* ff2_b  = (const float*)d_in[18];
    const float* ln2_g  = (const float*)d_in[19];
    const float* ln2_b  = (const float*)d_in[20];
    const float* u_w    = (const float*)d_in[21];
    const float* u_b    = (const float*)d_in[22];
    const float* h_w    = (const float*)d_in[23];
    const float* h_b    = (const float*)d_in[24];
    float* out = (float*)d_out;

    float *xs, *buf, *hraw;
    __half *xsh, *ath, *ffh, *whi, *wlo;
    cudaGetSymbolAddress((void**)&xs,   g_xs);
    cudaGetSymbolAddress((void**)&buf,  g_buf);
    cudaGetSymbolAddress((void**)&hraw, g_hraw);
    cudaGetSymbolAddress((void**)&xsh,  g_xsh);
    cudaGetSymbolAddress((void**)&ath,  g_ath);
    cudaGetSymbolAddress((void**)&ffh,  g_ffh);
    cudaGetSymbolAddress((void**)&whi,  g_whi);
    cudaGetSymbolAddress((void**)&wlo,  g_wlo);

    const int SM64 = 4 * (128*SSTH + 2*64*SSTH) * 2;   // 81920
    const int SM32 = 4 * (128*SSTH + 2*32*SSTH) * 2;   // 61440
    static bool attr_done = false;
    if (!attr_done) {
        cudaFuncSetAttribute(gemm_f16<64,0>, cudaFuncAttributeMaxDynamicSharedMemorySize, SM64);
        cudaFuncSetAttribute(gemm_f16<64,1>, cudaFuncAttributeMaxDynamicSharedMemorySize, SM64);
        cudaFuncSetAttribute(gemm_f16<32,0>, cudaFuncAttributeMaxDynamicSharedMemorySize, SM32);
        cudaFuncSetAttribute(gemm_f16<32,2>, cudaFuncAttributeMaxDynamicSharedMemorySize, SM32);
        cudaFuncSetAttribute(attn_kernel,    cudaFuncAttributeMaxDynamicSharedMemorySize, ATT_SM);
        attr_done = true;
    }

    const int MT = (NT + 127) / 128;   // 9

    split_all<<<4096, 256>>>((const float4*)qkv_w, (const float4*)out_w,
                             (const float4*)ff1_w, (const float4*)ff2_w,
                             (const float4*)u_w,   (const float4*)h_w);

    embed_kernel<<<NT, 256>>>(marg, conv_w, conv_b, fc_w, fc_b, ln0_g, ln0_b, pos);

    for (int l = 0; l < LL; l++) {
        gemm_f16<64,0><<<dim3((3*DD)/64, MT), 256, SM64>>>(
            xsh, whi + OFF_QKV + (size_t)l*3*DD*DD, wlo + OFF_QKV + (size_t)l*3*DD*DD,
            qkv_b + (size_t)l*3*DD, nullptr, buf, nullptr, nullptr, NT, 3*DD, DD);
        attn_kernel<<<dim3(BB, NH), 512, ATT_SM>>>(buf);
        gemm_f16<32,0><<<dim3(DD/32, MT), 256, SM32>>>(
            ath, whi + OFF_OUT + (size_t)l*DD*DD, wlo + OFF_OUT + (size_t)l*DD*DD,
            out_b + (size_t)l*DD, nullptr, buf, nullptr, nullptr, NT, DD, DD);
        resid_ln_kernel<<<NT/8, 256>>>(xs, buf, ln1_g + (size_t)l*DD, ln1_b + (size_t)l*DD);
        gemm_f16<64,1><<<dim3(DFFN/64, MT), 256, SM64>>>(
            xsh, whi + OFF_FF1 + (size_t)l*DFFN*DD, wlo + OFF_FF1 + (size_t)l*DFFN*DD,
            ff1_b + (size_t)l*DFFN, nullptr, nullptr, ffh, nullptr, NT, DFFN, DD);
        gemm_f16<32,0><<<dim3(DD/32, MT), 256, SM32>>>(
            ffh, whi + OFF_FF2 + (size_t)l*DD*DFFN, wlo + OFF_FF2 + (size_t)l*DD*DFFN,
            ff2_b + (size_t)l*DD, nullptr, buf, nullptr, nullptr, NT, DD, DFFN);
        resid_ln_kernel<<<NT/8, 256>>>(xs, buf, ln2_g + (size_t)l*DD, ln2_b + (size_t)l*DD);
    }

    gemm_f16<32,2><<<dim3((2*MM)/32, MT), 256, SM32>>>(
        xsh, whi + OFF_U, wlo + OFF_U, u_b, h_b,
        out, nullptr, hraw, NT, 2*MM, DD);

    hpot_kernel<<<dim3(BB, 64), 256>>>(marg, xg, out);
}

// round 17
// speedup vs baseline: 1.0245x; 1.0245x over previous
#include <cuda_runtime.h>
#include <cuda_fp16.h>
#include <math.h>
#include <stdint.h>

// ---------------- problem constants ----------------
#define BB    16
#define NP1   65
#define NT    (BB*NP1)      // 1040 tokens
#define MM    256
#define DD    512
#define NH    8
#define DH    64
#define LL    3
#define DFFN  2048
#define U_SIZE (NT*MM)

// weight-split buffer offsets (elements)
#define OFF_QKV 0
#define SZ_QKV  (LL*3*DD*DD)
#define OFF_OUT (OFF_QKV + SZ_QKV)
#define SZ_OUT  (LL*DD*DD)
#define OFF_FF1 (OFF_OUT + SZ_OUT)
#define SZ_FF1  (LL*DFFN*DD)
#define OFF_FF2 (OFF_FF1 + SZ_FF1)
#define SZ_FF2  (LL*DD*DFFN)
#define OFF_U   (OFF_FF2 + SZ_FF2)
#define SZ_U    (MM*DD)
#define OFF_H   (OFF_U + SZ_U)
#define SZ_H    (MM*DD)
#define WTOT    (OFF_H + SZ_H)

// ---------------- scratch ----------------
__device__ float  g_xs  [NT*DD];
__device__ __half g_xsh [NT*DD];
__device__ float  g_buf [NT*3*DD];      // proj / ff2 fp32 outputs
__device__ __half g_qkvh[NT*3*DD];      // qkv projection output (fp16)
__device__ __half g_ath [NT*DD];
__device__ __half g_ffh [NT*DFFN];
__device__ float  g_hraw[NT*MM];
__device__ __half g_whi[WTOT];
__device__ __half g_wlo[WTOT];

// ---------------- helpers ----------------
__device__ __forceinline__ float gelu_exact(float x) {
    return 0.5f * x * (1.0f + erff(x * 0.70710678118654752440f));
}
__device__ __forceinline__ float blockSum256(float v, float* sm) {
    int tid = threadIdx.x;
    #pragma unroll
    for (int o = 16; o > 0; o >>= 1) v += __shfl_down_sync(0xffffffffu, v, o);
    if ((tid & 31) == 0) sm[tid >> 5] = v;
    __syncthreads();
    if (tid < 8) {
        v = sm[tid];
        #pragma unroll
        for (int o = 4; o > 0; o >>= 1) v += __shfl_down_sync(0xffu, v, o);
        if (tid == 0) sm[0] = v;
    }
    __syncthreads();
    float r = sm[0];
    __syncthreads();
    return r;
}
__device__ __forceinline__ float warpSum(float v) {
    #pragma unroll
    for (int o = 16; o > 0; o >>= 1) v += __shfl_xor_sync(0xffffffffu, v, o);
    return v;
}
__device__ __forceinline__ void mma16h(float* d, const uint32_t* a, const uint32_t* b) {
    asm volatile(
        "mma.sync.aligned.m16n8k16.row.col.f32.f16.f16.f32 "
        "{%0,%1,%2,%3}, {%4,%5,%6,%7}, {%8,%9}, {%0,%1,%2,%3};"
        : "+f"(d[0]), "+f"(d[1]), "+f"(d[2]), "+f"(d[3])
        : "r"(a[0]), "r"(a[1]), "r"(a[2]), "r"(a[3]), "r"(b[0]), "r"(b[1]));
}
__device__ __forceinline__ void ldsm4(uint32_t* r, uint32_t addr) {
    asm volatile("ldmatrix.sync.aligned.m8n8.x4.shared.b16 {%0,%1,%2,%3}, [%4];"
                 : "=r"(r[0]), "=r"(r[1]), "=r"(r[2]), "=r"(r[3]) : "r"(addr));
}
__device__ __forceinline__ uint32_t smem_u32(const void* p) {
    uint32_t a;
    asm("{ .reg .u64 t; cvta.to.shared.u64 t, %1; cvt.u32.u64 %0, t; }" : "=r"(a) : "l"(p));
    return a;
}
__device__ __forceinline__ void cp16(uint32_t dst, const void* src, unsigned ok) {
    asm volatile("cp.async.cg.shared.global [%0], [%1], 16, %2;"
                 :: "r"(dst), "l"(src), "r"(ok));
}
__device__ __forceinline__ void cp16u(uint32_t dst, const void* src) {
    asm volatile("cp.async.cg.shared.global [%0], [%1], 16;"
                 :: "r"(dst), "l"(src));
}

// ---------------- fused weight split (fp16 hi/lo) ----------------
#define B0 (SZ_QKV/4)
#define B1 (B0 + SZ_OUT/4)
#define B2 (B1 + SZ_FF1/4)
#define B3 (B2 + SZ_FF2/4)
#define B4 (B3 + SZ_U/4)
#define B5 (B4 + SZ_H/4)
__global__ void split_all(const float4* __restrict__ w_qkv, const float4* __restrict__ w_out,
                          const float4* __restrict__ w_ff1, const float4* __restrict__ w_ff2,
                          const float4* __restrict__ w_u,   const float4* __restrict__ w_h) {
    __half2* hi = (__half2*)g_whi;
    __half2* lo = (__half2*)g_wlo;
    for (int i = blockIdx.x*blockDim.x + threadIdx.x; i < B5; i += gridDim.x*blockDim.x) {
        const float4* src; int j;
        if      (i < B0) { src = w_qkv; j = i; }
        else if (i < B1) { src = w_out; j = i - B0; }
        else if (i < B2) { src = w_ff1; j = i - B1; }
        else if (i < B3) { src = w_ff2; j = i - B2; }
        else if (i < B4) { src = w_u;   j = i - B3; }
        else             { src = w_h;   j = i - B4; }
        float4 v = src[j];
        __half hx = __float2half_rn(v.x), hy = __float2half_rn(v.y);
        __half hz = __float2half_rn(v.z), hw = __float2half_rn(v.w);
        __half lx = __float2half_rn(v.x - __half2float(hx));
        __half ly = __float2half_rn(v.y - __half2float(hy));
        __half lz = __float2half_rn(v.z - __half2float(hz));
        __half lw = __float2half_rn(v.w - __half2float(hw));
        hi[2*i]   = __halves2half2(hx, hy);
        hi[2*i+1] = __halves2half2(hz, hw);
        lo[2*i]   = __halves2half2(lx, ly);
        lo[2*i+1] = __halves2half2(lz, lw);
    }
}

// ---------------- embed ----------------
__global__ void embed_kernel(const float* __restrict__ marg,
                             const float* __restrict__ conv_w,
                             const float* __restrict__ conv_b,
                             const float* __restrict__ fc_w,
                             const float* __restrict__ fc_b,
                             const float* __restrict__ ln_g,
                             const float* __restrict__ ln_b,
                             const float* __restrict__ pos) {
    int t   = blockIdx.x;
    int tid = threadIdx.x;
    __shared__ float red[8];
    __shared__ float e128[128];

    const float* x = marg + (size_t)t * MM;
    float S = blockSum256(x[tid], red);

    if (tid < 128) {
        float x0 = x[0], x1 = x[1], x254 = x[254], x255 = x[255];
        float T0 = S - x254 - x255;
        float T1 = S - x255;
        float T2 = S;
        float T3 = S - x0;
        float T4 = S - x0 - x1;
        const float* w = conv_w + tid * 5;
        e128[tid] = conv_b[tid] +
            (w[0]*T0 + w[1]*T1 + w[2]*T2 + w[3]*T3 + w[4]*T4) * (1.0f/256.0f);
    }
    __syncthreads();

    float y0 = fc_b[tid];
    float y1 = fc_b[tid + 256];
    #pragma unroll 8
    for (int k = 0; k < 128; k++) {
        float e = e128[k];
        y0 = fmaf(e, fc_w[k*DD + tid],       y0);
        y1 = fmaf(e, fc_w[k*DD + tid + 256], y1);
    }
    float s  = blockSum256(y0 + y1, red);
    float mu = s * (1.0f/512.0f);
    float d0 = y0 - mu, d1 = y1 - mu;
    float vs = blockSum256(d0*d0 + d1*d1, red);
    float inv = rsqrtf(vs * (1.0f/512.0f) + 1e-5f);

    int p = t % NP1;
    float z0 = gelu_exact(d0*inv*ln_g[tid]       + ln_b[tid])       + pos[p*DD + tid];
    float z1 = gelu_exact(d1*inv*ln_g[tid + 256] + ln_b[tid + 256]) + pos[p*DD + tid + 256];
    size_t i0 = (size_t)t*DD + tid, i1 = i0 + 256;
    g_xs[i0] = z0; g_xs[i1] = z1;
    g_xsh[i0] = __float2half_rn(z0);
    g_xsh[i1] = __float2half_rn(z1);
}

// ---------------- 2-term fp16 mma.sync GEMM, BM=128, BK=32, 4-stage ring ----------------
// MODE 0: fp32+bias. MODE 1: gelu+half. MODE 2: dual heads. MODE 3: bias+half.
#define SSTH 40
template <int BN, int MODE>
__global__ void __launch_bounds__(256, 2)
gemm_f16(const __half* __restrict__ A,
         const __half* __restrict__ Whi, const __half* __restrict__ Wlo,
         const float* __restrict__ bias, const float* __restrict__ bias2,
         float* __restrict__ C, __half* __restrict__ Ch, float* __restrict__ C2,
         int M, int N, int K) {
    constexpr int MFRAG = 2;
    constexpr int NFRAG = BN / 16;
    constexpr int A_E   = 128 * SSTH;
    constexpr int B_E   = BN * SSTH;
    constexpr int STAGE_E = A_E + 2*B_E;

    extern __shared__ __align__(16) __half sm[];
    const int tid  = threadIdx.x;
    const int warp = tid >> 5, lane = tid & 31;
    const int gid  = lane >> 2, tig = lane & 3;
    const int m_warp = (warp & 3) * 32;
    const int n_warp = (warp >> 2) * (BN/2);
    const int bn = blockIdx.x * BN;
    const int bm = blockIdx.y * 128;

    float acc[MFRAG][NFRAG][4];
    #pragma unroll
    for (int mi = 0; mi < MFRAG; mi++)
        #pragma unroll
        for (int ni = 0; ni < NFRAG; ni++)
            #pragma unroll
            for (int r = 0; r < 4; r++) acc[mi][ni][r] = 0.0f;

    const uint32_t smb = smem_u32(sm);

    const int laneA_row = m_warp + ((lane >> 3) & 1) * 8 + (lane & 7);
    const int laneA_col = (lane >> 4) * 8;
    const int laneB_row = n_warp + ((lane >> 4) & 1) * 8 + (lane & 7);
    const int laneB_col = ((lane >> 3) & 1) * 8;

    const int rowA = tid >> 2;
    const int chkA = tid & 3;
    const int T = K >> 5;

    auto load_tile = [&](int stage, int k0) {
        uint32_t sb = smb + (uint32_t)stage * (STAGE_E*2);
        #pragma unroll
        for (int i = 0; i < 2; i++) {
            int row = rowA + i*64;
            int gr  = bm + row;
            unsigned ok = (gr < M) ? 16u : 0u;
            size_t go = (size_t)(gr < M ? gr : 0) * K + k0 + chkA*8;
            cp16(sb + (uint32_t)(row*SSTH + chkA*8)*2, A + go, ok);
        }
        {
            int nb = BN * 4;
            if (BN == 64 || tid < nb) {
                int row = (BN == 64) ? rowA : (tid >> 2);
                int chk = (BN == 64) ? chkA : (tid & 3);
                size_t go = (size_t)(bn + row) * K + k0 + chk*8;
                uint32_t d = sb + (uint32_t)(A_E + row*SSTH + chk*8)*2;
                cp16u(d,         Whi + go);
                cp16u(d + B_E*2, Wlo + go);
            }
        }
        asm volatile("cp.async.commit_group;");
    };

    load_tile(0, 0);
    if (T > 1) load_tile(1, 32);
    if (T > 2) load_tile(2, 64);

    for (int t = 0; t < T; t++) {
        int rem = T - 1 - t; if (rem > 2) rem = 2;
        if      (rem == 2) asm volatile("cp.async.wait_group 2;");
        else if (rem == 1) asm volatile("cp.async.wait_group 1;");
        else               asm volatile("cp.async.wait_group 0;");
        __syncthreads();
        if (t + 3 < T) load_tile((t + 3) & 3, (t + 3) * 32);

        const uint32_t stage_b = smb + (uint32_t)(t & 3) * (STAGE_E*2);

        #pragma unroll
        for (int kf = 0; kf < 2; kf++) {
            const int kcol = kf * 16;
            uint32_t ah[MFRAG][4];
            uint32_t aoff = stage_b + (uint32_t)(laneA_row*SSTH + kcol + laneA_col)*2;
            #pragma unroll
            for (int mi = 0; mi < MFRAG; mi++)
                ldsm4(ah[mi], aoff + (uint32_t)(mi*16*SSTH)*2);

            uint32_t bh[NFRAG][2], bl[NFRAG][2];
            uint32_t boff = stage_b + (uint32_t)(A_E)*2
                          + (uint32_t)(laneB_row*SSTH + kcol + laneB_col)*2;
            #pragma unroll
            for (int ng = 0; ng < NFRAG/2; ng++) {
                uint32_t rb[4], rl[4];
                ldsm4(rb, boff + (uint32_t)(ng*16*SSTH)*2);
                ldsm4(rl, boff + (uint32_t)(ng*16*SSTH)*2 + B_E*2);
                bh[2*ng][0]   = rb[0]; bh[2*ng][1]   = rb[1];
                bh[2*ng+1][0] = rb[2]; bh[2*ng+1][1] = rb[3];
                bl[2*ng][0]   = rl[0]; bl[2*ng][1]   = rl[1];
                bl[2*ng+1][0] = rl[2]; bl[2*ng+1][1] = rl[3];
            }
            #pragma unroll
            for (int mi = 0; mi < MFRAG; mi++)
                #pragma unroll
                for (int ni = 0; ni < NFRAG; ni++) mma16h(acc[mi][ni], ah[mi], bh[ni]);
            #pragma unroll
            for (int mi = 0; mi < MFRAG; mi++)
                #pragma unroll
                for (int ni = 0; ni < NFRAG; ni++) mma16h(acc[mi][ni], ah[mi], bl[ni]);
        }
    }

    #pragma unroll
    for (int mi = 0; mi < MFRAG; mi++) {
        #pragma unroll
        for (int ni = 0; ni < NFRAG; ni++) {
            int col = bn + n_warp + ni*8 + tig*2;
            float* a4 = acc[mi][ni];
            #pragma unroll
            for (int half_ = 0; half_ < 2; half_++) {
                int r = bm + m_warp + mi*16 + gid + half_*8;
                if (r >= M) continue;
                float v0 = a4[half_*2];
                float v1 = a4[half_*2+1];
                if (MODE == 0) {
                    v0 += __ldg(bias + col); v1 += __ldg(bias + col + 1);
                    *(float2*)&C[(size_t)r*N + col] = make_float2(v0, v1);
                } else if (MODE == 1) {
                    v0 = gelu_exact(v0 + __ldg(bias + col));
                    v1 = gelu_exact(v1 + __ldg(bias + col + 1));
                    *(__half2*)&Ch[(size_t)r*N + col] =
                        __halves2half2(__float2half_rn(v0), __float2half_rn(v1));
                } else if (MODE == 3) {
                    v0 += __ldg(bias + col); v1 += __ldg(bias + col + 1);
                    *(__half2*)&Ch[(size_t)r*N + col] =
                        __halves2half2(__float2half_rn(v0), __float2half_rn(v1));
                } else {
                    if (col < 256) {
                        v0 += __ldg(bias + col); v1 += __ldg(bias + col + 1);
                        *(float2*)&C[(size_t)r*MM + col] = make_float2(v0, v1);
                    } else {
                        v0 += __ldg(bias2 + col - 256); v1 += __ldg(bias2 + col - 255);
                        *(float2*)&C2[(size_t)r*MM + col - 256] = make_float2(v0, v1);
                    }
                }
            }
        }
    }
}

// ---------------- attention: one 512-thread block per (b,h), half-staged QKV ----------------
#define QPAD 68
#define ATT_SM (4 * NP1 * QPAD * 4)   // sq, sk, sv, ss = 70720 bytes
__global__ void __launch_bounds__(512, 1) attn_kernel(const __half* __restrict__ qkv) {
    int b = blockIdx.x, h = blockIdx.y;
    extern __shared__ float asm_[];
    float* sq = asm_;
    float* sk = sq + NP1*QPAD;
    float* sv = sk + NP1*QPAD;
    float* ss = sv + NP1*QPAD;
    int tid = threadIdx.x;
    int warp = tid >> 5, lane = tid & 31;

    // stage Q, K, V: load 8 halves (16B) per chunk, convert to fp32 smem
    const __half* base_b = qkv + (size_t)b * NP1 * (3*DD) + h*DH;
    for (int idx = tid; idx < NP1*8; idx += 512) {
        int t = idx >> 3, c8 = (idx & 7) * 8;
        const __half* rowp = base_b + (size_t)t * (3*DD) + c8;
        #pragma unroll
        for (int m = 0; m < 3; m++) {
            uint4 raw = __ldg((const uint4*)(rowp + m*DD));
            const __half2* hp = (const __half2*)&raw;
            float2 f0 = __half22float2(hp[0]);
            float2 f1 = __half22float2(hp[1]);
            float2 f2 = __half22float2(hp[2]);
            float2 f3 = __half22float2(hp[3]);
            float* dst = (m == 0 ? sq : (m == 1 ? sk : sv)) + t*QPAD + c8;
            *(float4*)dst       = make_float4(f0.x, f0.y, f1.x, f1.y);
            *(float4*)(dst + 4) = make_float4(f2.x, f2.y, f3.x, f3.y);
        }
    }
    __syncthreads();

    // scores
    const float scale = 0.125f;
    for (int idx = tid; idx < NP1*NP1; idx += 512) {
        int r = idx / NP1, c = idx - r*NP1;
        const float4* qr = (const float4*)&sq[r*QPAD];
        const float4* kr = (const float4*)&sk[c*QPAD];
        float s0 = 0.f, s1 = 0.f, s2 = 0.f, s3 = 0.f;
        #pragma unroll
        for (int d = 0; d < 16; d += 4) {
            float4 a0 = qr[d],   b0 = kr[d];
            float4 a1 = qr[d+1], b1 = kr[d+1];
            float4 a2 = qr[d+2], b2 = kr[d+2];
            float4 a3 = qr[d+3], b3 = kr[d+3];
            s0 += a0.x*b0.x + a0.y*b0.y + a0.z*b0.z + a0.w*b0.w;
            s1 += a1.x*b1.x + a1.y*b1.y + a1.z*b1.z + a1.w*b1.w;
            s2 += a2.x*b2.x + a2.y*b2.y + a2.z*b2.z + a2.w*b2.w;
            s3 += a3.x*b3.x + a3.y*b3.y + a3.z*b3.z + a3.w*b3.w;
        }
        ss[r*QPAD + c] = (s0 + s1 + s2 + s3) * scale;
    }
    __syncthreads();

    // warp-parallel softmax: 65 rows over 16 warps
    for (int r = warp; r < NP1; r += 16) {
        float* rowp = ss + r*QPAD;
        float m = -1e30f;
        for (int c = lane; c < NP1; c += 32) m = fmaxf(m, rowp[c]);
        #pragma unroll
        for (int o = 16; o > 0; o >>= 1) m = fmaxf(m, __shfl_xor_sync(0xffffffffu, m, o));
        float s = 0.0f;
        for (int c = lane; c < NP1; c += 32) { float e = __expf(rowp[c] - m); rowp[c] = e; s += e; }
        #pragma unroll
        for (int o = 16; o > 0; o >>= 1) s += __shfl_xor_sync(0xffffffffu, s, o);
        float inv = 1.0f / s;
        for (int c = lane; c < NP1; c += 32) rowp[c] *= inv;
    }
    __syncthreads();

    // O = att @ V
    for (int idx = tid; idx < NP1*16; idx += 512) {
        int r = idx >> 4, d4 = (idx & 15) * 4;
        const float* rowp = ss + r*QPAD;
        float4 o0 = make_float4(0.f, 0.f, 0.f, 0.f);
        float4 o1 = make_float4(0.f, 0.f, 0.f, 0.f);
        int t = 0;
        #pragma unroll 8
        for (; t + 2 <= NP1; t += 2) {
            float w0 = rowp[t], w1 = rowp[t+1];
            float4 v0 = *(const float4*)&sv[t*QPAD + d4];
            float4 v1 = *(const float4*)&sv[(t+1)*QPAD + d4];
            o0.x = fmaf(w0, v0.x, o0.x); o0.y = fmaf(w0, v0.y, o0.y);
            o0.z = fmaf(w0, v0.z, o0.z); o0.w = fmaf(w0, v0.w, o0.w);
            o1.x = fmaf(w1, v1.x, o1.x); o1.y = fmaf(w1, v1.y, o1.y);
            o1.z = fmaf(w1, v1.z, o1.z); o1.w = fmaf(w1, v1.w, o1.w);
        }
        {
            float w0 = rowp[64];
            float4 v0 = *(const float4*)&sv[64*QPAD + d4];
            o0.x = fmaf(w0, v0.x, o0.x); o0.y = fmaf(w0, v0.y, o0.y);
            o0.z = fmaf(w0, v0.z, o0.z); o0.w = fmaf(w0, v0.w, o0.w);
        }
        __half2 p0 = __halves2half2(__float2half_rn(o0.x + o1.x), __float2half_rn(o0.y + o1.y));
        __half2 p1 = __halves2half2(__float2half_rn(o0.z + o1.z), __float2half_rn(o0.w + o1.w));
        size_t gi = (size_t)(b*NP1 + r)*DD + h*DH + d4;
        *(__half2*)&g_ath[gi]     = p0;
        *(__half2*)&g_ath[gi + 2] = p1;
    }
}

// ---------------- residual add + layernorm: warp-per-row ----------------
__global__ void __launch_bounds__(256) resid_ln_kernel(float* __restrict__ xs,
                                const float* __restrict__ add,
                                const float* __restrict__ g,
                                const float* __restrict__ bb) {
    int warp = threadIdx.x >> 5, lane = threadIdx.x & 31;
    int t = blockIdx.x * 8 + warp;
    size_t base = (size_t)t * DD;

    float4 v[4];
    #pragma unroll
    for (int k = 0; k < 4; k++) {
        int c = (lane + k*32) * 4;
        float4 a  = *(const float4*)&xs[base + c];
        float4 ad = *(const float4*)&add[base + c];
        v[k] = make_float4(a.x+ad.x, a.y+ad.y, a.z+ad.z, a.w+ad.w);
    }
    float s = 0.f;
    #pragma unroll
    for (int k = 0; k < 4; k++) s += (v[k].x + v[k].y) + (v[k].z + v[k].w);
    s = warpSum(s);
    float mu = s * (1.0f/512.0f);
    float vs = 0.f;
    #pragma unroll
    for (int k = 0; k < 4; k++) {
        float dx = v[k].x-mu, dy = v[k].y-mu, dz = v[k].z-mu, dw = v[k].w-mu;
        vs += dx*dx + dy*dy + dz*dz + dw*dw;
    }
    vs = warpSum(vs);
    float inv = rsqrtf(vs * (1.0f/512.0f) + 1e-5f);

    #pragma unroll
    for (int k = 0; k < 4; k++) {
        int c = (lane + k*32) * 4;
        float4 gg = *(const float4*)&g[c];
        float4 bv = *(const float4*)&bb[c];
        float z0 = (v[k].x - mu)*inv*gg.x + bv.x;
        float z1 = (v[k].y - mu)*inv*gg.y + bv.y;
        float z2 = (v[k].z - mu)*inv*gg.z + bv.z;
        float z3 = (v[k].w - mu)*inv*gg.w + bv.w;
        *(float4*)&xs[base + c] = make_float4(z0, z1, z2, z3);
        __half2 h0 = __halves2half2(__float2half_rn(z0), __float2half_rn(z1));
        __half2 h1 = __halves2half2(__float2half_rn(z2), __float2half_rn(z3));
        *(__half2*)&g_xsh[base + c]     = h0;
        *(__half2*)&g_xsh[base + c + 2] = h1;
    }
}

// ---------------- final drift / correction -> h_pot ----------------
__global__ void hpot_kernel(const float* __restrict__ marg,
                            const float* __restrict__ xg,
                            float* __restrict__ out) {
    int b = blockIdx.x, n = blockIdx.y;
    int i = threadIdx.x;
    __shared__ float red[8];

    float x0   = __ldg(xg);
    float xend = __ldg(xg + 255);
    float delta = (xend - x0) * (1.0f/255.0f);
    float xi = __ldg(xg + i);

    float hr = g_hraw[(size_t)(b*NP1 + n)*MM + i];
    float u  = hr * 100.0f * delta;
    float Mv;
    if (fabsf(u) < 1e-3f) {
        Mv = 127.5f - u*5461.25f + u*u*u*5965232.4f;
    } else {
        Mv = 1.0f/expm1f(u) - 256.0f/expm1f(256.0f*u);
    }
    float drift = (x0 + delta*Mv) - xi;

    float mu = marg[(size_t)(b*NP1 + n)*MM + i];
    float wd = blockSum256(mu * drift, red);
    float wm = blockSum256(mu, red);
    float corr = wd / (wm + 1e-8f);
    out[U_SIZE + (size_t)(b*64 + n)*MM + i] = hr - corr;
}

// ---------------- launch ----------------
extern "C" void kernel_launch(void* const* d_in, const int* in_sizes, int n_in,
                              void* d_out, int out_size) {
    const float* marg   = (const float*)d_in[0];
    const float* xg     = (const float*)d_in[1];
    const float* conv_w = (const float*)d_in[2];
    const float* conv_b = (const float*)d_in[3];
    const float* fc_w   = (const float*)d_in[4];
    const float* fc_b   = (const float*)d_in[5];
    const float* ln0_g  = (const float*)d_in[6];
    const float* ln0_b  = (const float*)d_in[7];
    const float* pos    = (const float*)d_in[8];
    const float* qkv_w  = (const float*)d_in[9];
    const float* qkv_b  = (const float*)d_in[10];
    const float* out_w  = (const float*)d_in[11];
    const float* out_b  = (const float*)d_in[12];
    const float* ln1_g  = (const float*)d_in[13];
    const float* ln1_b  = (const float*)d_in[14];
    const float* ff1_w  = (const float*)d_in[15];
    const float* ff1_b  = (const float*)d_in[16];
    const float* ff2_w  = (const float*)d_in[17];
    const float* ff2_b  = (const float*)d_in[18];
    const float* ln2_g  = (const float*)d_in[19];
    const float* ln2_b  = (const float*)d_in[20];
    const float* u_w    = (const float*)d_in[21];
    const float* u_b    = (const float*)d_in[22];
    const float* h_w    = (const float*)d_in[23];
    const float* h_b    = (const float*)d_in[24];
    float* out = (float*)d_out;

    float *xs, *buf, *hraw;
    __half *xsh, *qkvh, *ath, *ffh, *whi, *wlo;
    cudaGetSymbolAddress((void**)&xs,   g_xs);
    cudaGetSymbolAddress((void**)&buf,  g_buf);
    cudaGetSymbolAddress((void**)&hraw, g_hraw);
    cudaGetSymbolAddress((void**)&xsh,  g_xsh);
    cudaGetSymbolAddress((void**)&qkvh, g_qkvh);
    cudaGetSymbolAddress((void**)&ath,  g_ath);
    cudaGetSymbolAddress((void**)&ffh,  g_ffh);
    cudaGetSymbolAddress((void**)&whi,  g_whi);
    cudaGetSymbolAddress((void**)&wlo,  g_wlo);

    const int SM64 = 4 * (128*SSTH + 2*64*SSTH) * 2;   // 81920
    const int SM32 = 4 * (128*SSTH + 2*32*SSTH) * 2;   // 61440
    static bool attr_done = false;
    if (!attr_done) {
        cudaFuncSetAttribute(gemm_f16<64,3>, cudaFuncAttributeMaxDynamicSharedMemorySize, SM64);
        cudaFuncSetAttribute(gemm_f16<64,1>, cudaFuncAttributeMaxDynamicSharedMemorySize, SM64);
        cudaFuncSetAttribute(gemm_f16<32,0>, cudaFuncAttributeMaxDynamicSharedMemorySize, SM32);
        cudaFuncSetAttribute(gemm_f16<32,2>, cudaFuncAttributeMaxDynamicSharedMemorySize, SM32);
        cudaFuncSetAttribute(attn_kernel,    cudaFuncAttributeMaxDynamicSharedMemorySize, ATT_SM);
        attr_done = true;
    }

    const int MT = (NT + 127) / 128;   // 9

    split_all<<<4096, 256>>>((const float4*)qkv_w, (const float4*)out_w,
                             (const float4*)ff1_w, (const float4*)ff2_w,
                             (const float4*)u_w,   (const float4*)h_w);

    embed_kernel<<<NT, 256>>>(marg, conv_w, conv_b, fc_w, fc_b, ln0_g, ln0_b, pos);

    for (int l = 0; l < LL; l++) {
        gemm_f16<64,3><<<dim3((3*DD)/64, MT), 256, SM64>>>(
            xsh, whi + OFF_QKV + (size_t)l*3*DD*DD, wlo + OFF_QKV + (size_t)l*3*DD*DD,
            qkv_b + (size_t)l*3*DD, nullptr, nullptr, qkvh, nullptr, NT, 3*DD, DD);
        attn_kernel<<<dim3(BB, NH), 512, ATT_SM>>>(qkvh);
        gemm_f16<32,0><<<dim3(DD/32, MT), 256, SM32>>>(
            ath, whi + OFF_OUT + (size_t)l*DD*DD, wlo + OFF_OUT + (size_t)l*DD*DD,
            out_b + (size_t)l*DD, nullptr, buf, nullptr, nullptr, NT, DD, DD);
        resid_ln_kernel<<<NT/8, 256>>>(xs, buf, ln1_g + (size_t)l*DD, ln1_b + (size_t)l*DD);
        gemm_f16<64,1><<<dim3(DFFN/64, MT), 256, SM64>>>(
            xsh, whi + OFF_FF1 + (size_t)l*DFFN*DD, wlo + OFF_FF1 + (size_t)l*DFFN*DD,
            ff1_b + (size_t)l*DFFN, nullptr, nullptr, ffh, nullptr, NT, DFFN, DD);
        gemm_f16<32,0><<<dim3(DD/32, MT), 256, SM32>>>(
            ffh, whi + OFF_FF2 + (size_t)l*DD*DFFN, wlo + OFF_FF2 + (size_t)l*DD*DFFN,
            ff2_b + (size_t)l*DD, nullptr, buf, nullptr, nullptr, NT, DD, DFFN);
        resid_ln_kernel<<<NT/8, 256>>>(xs, buf, ln2_g + (size_t)l*DD, ln2_b + (size_t)l*DD);
    }

    gemm_f16<32,2><<<dim3((2*MM)/32, MT), 256, SM32>>>(
        xsh, whi + OFF_U, wlo + OFF_U, u_b, h_b,
        out, nullptr, hraw, NT, 2*MM, DD);

    hpot_kernel<<<dim3(BB, 64), 256>>>(marg, xg, out);
}